// round 12
// baseline (speedup 1.0000x reference)
#include <cuda_runtime.h>
#include <cuda_fp16.h>
#include <cstdint>

#define Bn  4
#define Ln  1024
#define Dn  768
#define Hn  6
#define DHn 128
#define BHn (Bn*Hn)
#define EPSf 1e-5f
#define GLDH 136   /* half leading dim: 128 + 8 */

#define OFF_CO 0
#define OFF_W  (BHn*Ln*Ln)          /* 25165824 */
#define OFF_V  (OFF_W + Bn*Ln)      /* 25169920 */

// ---------------- scratch ----------------
__device__ float  g_q2[BHn*Ln];
__device__ float  g_k2[BHn*Ln];
__device__ double g_sum1[Hn];
__device__ double g_sumsq1[Hn];
__device__ float  g_w[BHn*Ln];
__device__ unsigned char g_valid[Bn*Ln];

// ---------------- PTX: ldmatrix + mma ----------------
__device__ __forceinline__ void ldsm_x4(uint32_t& r0, uint32_t& r1, uint32_t& r2, uint32_t& r3,
                                        uint32_t addr) {
    asm volatile("ldmatrix.sync.aligned.m8n8.x4.shared.b16 {%0,%1,%2,%3}, [%4];"
                 : "=r"(r0), "=r"(r1), "=r"(r2), "=r"(r3) : "r"(addr));
}
__device__ __forceinline__ void mma16816(float* c, uint32_t a0, uint32_t a1, uint32_t a2,
                                         uint32_t a3, uint32_t b0, uint32_t b1) {
    asm volatile("mma.sync.aligned.m16n8k16.row.col.f32.f16.f16.f32 "
                 "{%0,%1,%2,%3}, {%4,%5,%6,%7}, {%8,%9}, {%0,%1,%2,%3};"
                 : "+f"(c[0]), "+f"(c[1]), "+f"(c[2]), "+f"(c[3])
                 : "r"(a0), "r"(a1), "r"(a2), "r"(a3), "r"(b0), "r"(b1));
}
__device__ __forceinline__ uint32_t smem_u32(const void* p) {
    return (uint32_t)__cvta_generic_to_shared(p);
}

// ---------------- sq + prep fused ----------------
__global__ void sq_kernel(const float* __restrict__ Q, const float* __restrict__ K,
                          const unsigned int* __restrict__ w) {
    if (blockIdx.x >= 1024) {
        int bidx = blockIdx.x - 1024;
        if (bidx < 96) {
            int idx = bidx*256 + threadIdx.x;
            g_w[idx] = 0.f;
            if (idx < Hn) { g_sum1[idx] = 0.0; g_sumsq1[idx] = 0.0; }
            return;
        }
        __shared__ int s_float, s_byte;
        if (threadIdx.x == 0) { s_float = 0; s_byte = 0; }
        __syncthreads();
        for (int i = threadIdx.x; i < (Bn*Ln)/4; i += blockDim.x) {
            unsigned v = w[i];
            if (v == 0x3f800000u) atomicOr(&s_float, 1);
            else if (v > 1u)      atomicOr(&s_byte, 1);
        }
        __syncthreads();
        int byte_mode = (!s_float) && s_byte;
        const unsigned char* bytes = (const unsigned char*)w;
        for (int i = threadIdx.x; i < Bn*Ln; i += blockDim.x) {
            bool padded = byte_mode ? (bytes[i] != 0) : (w[i] != 0u);
            g_valid[i] = padded ? 0 : 1;
        }
        return;
    }
    int gw = (blockIdx.x*blockDim.x + threadIdx.x) >> 5;
    int lane = threadIdx.x & 31;
    int t = gw / (Bn*Ln);
    int r = gw % (Bn*Ln);
    const float* src = (t ? K : Q) + (size_t)r*Dn;
    float* dst = t ? g_k2 : g_q2;
    int b = r >> 10, l = r & (Ln-1);
    float4 x[Hn];
    #pragma unroll
    for (int hh = 0; hh < Hn; hh++) x[hh] = ((const float4*)src)[hh*32 + lane];
    #pragma unroll
    for (int hh = 0; hh < Hn; hh++) {
        float s = x[hh].x*x[hh].x + x[hh].y*x[hh].y + x[hh].z*x[hh].z + x[hh].w*x[hh].w;
        #pragma unroll
        for (int o = 16; o; o >>= 1) s += __shfl_xor_sync(0xffffffffu, s, o);
        if (lane == 0) dst[(b*Hn + hh)*Ln + l] = s;
    }
}

// ---------------- Vh output: transpose copy ----------------
__global__ void vout_kernel(const float* __restrict__ V, float* __restrict__ out) {
    int idx = blockIdx.x*blockDim.x + threadIdx.x;
    if (idx >= BHn*Ln*DHn/4) return;
    int d4 = idx & 31;
    int l  = (idx >> 5) & (Ln-1);
    int h  = (idx >> 15) % Hn;
    int b  = idx / (32*Ln*Hn);
    float4 v = *(const float4*)(V + ((size_t)(b*Ln + l))*Dn + h*DHn + d4*4);
    ((float4*)(out + OFF_V))[idx] = v;
}

// ---------------- main GEMM (raw mma): S = 2QK^T - q2 - k2 -> co, + BN1 stats ----------------
// CTA 128x128, 256 threads, warp tile 32x64 (4x2), register epilogue, 2 CTAs/SM.
__global__ void __launch_bounds__(256, 2) gemm_kernel(const float* __restrict__ Q,
                                                      const float* __restrict__ K,
                                                      float* __restrict__ co) {
    extern __shared__ char smraw[];
    __half* As = (__half*)smraw;                    // 128 x GLDH
    __half* Bs = As + 128*GLDH;
    __shared__ float q2s[128], k2s[128];
    __shared__ double rs[8], rq[8];

    int bh = blockIdx.z; int b = bh / Hn, h = bh % Hn;
    int bi0 = blockIdx.y*128, bj0 = blockIdx.x*128;
    const float* Qb = Q + (size_t)b*Ln*Dn + h*DHn;
    const float* Kb = K + (size_t)b*Ln*Dn + h*DHn;
    int tid = threadIdx.x, warp = tid >> 5, lane = tid & 31;

    if (tid < 128) q2s[tid] = g_q2[bh*Ln + bi0 + tid];
    else k2s[tid - 128] = g_k2[bh*Ln + bj0 + tid - 128];

    #pragma unroll
    for (int i = 0; i < 16; i++) {
        int t = tid + i*256;
        int r = t >> 5, c = t & 31;
        float4 q = *(const float4*)(Qb + (size_t)(bi0 + r)*Dn + c*4);
        *(half2*)&As[r*GLDH + c*4 + 0] = __floats2half2_rn(q.x, q.y);
        *(half2*)&As[r*GLDH + c*4 + 2] = __floats2half2_rn(q.z, q.w);
    }
    #pragma unroll
    for (int i = 0; i < 16; i++) {
        int t = tid + i*256;
        int r = t >> 5, c = t & 31;
        float4 k = *(const float4*)(Kb + (size_t)(bj0 + r)*Dn + c*4);
        *(half2*)&Bs[r*GLDH + c*4 + 0] = __floats2half2_rn(k.x, k.y);
        *(half2*)&Bs[r*GLDH + c*4 + 2] = __floats2half2_rn(k.z, k.w);
    }
    __syncthreads();

    int wm = warp & 3, wn = warp >> 2;          // 4 M-warps x 2 N-warps
    uint32_t aBase = smem_u32(As) +
        (uint32_t)(((wm*32 + (lane & 15))*GLDH + (lane >> 4)*8) * 2);
    uint32_t bBase = smem_u32(Bs) +
        (uint32_t)(((wn*64 + (lane & 7) + ((lane >> 4) << 3))*GLDH + ((lane >> 3) & 1)*8) * 2);

    float acc[2][8][4];
    #pragma unroll
    for (int mi = 0; mi < 2; mi++)
        #pragma unroll
        for (int ni = 0; ni < 8; ni++)
            #pragma unroll
            for (int e = 0; e < 4; e++) acc[mi][ni][e] = 0.f;

    #pragma unroll
    for (int k = 0; k < 128; k += 16) {
        uint32_t a[2][4], bb[4][4];
        #pragma unroll
        for (int mi = 0; mi < 2; mi++)
            ldsm_x4(a[mi][0], a[mi][1], a[mi][2], a[mi][3],
                    aBase + (uint32_t)((mi*16*GLDH + k)*2));
        #pragma unroll
        for (int nj = 0; nj < 4; nj++)
            ldsm_x4(bb[nj][0], bb[nj][1], bb[nj][2], bb[nj][3],
                    bBase + (uint32_t)((nj*16*GLDH + k)*2));
        #pragma unroll
        for (int mi = 0; mi < 2; mi++)
            #pragma unroll
            for (int ni = 0; ni < 8; ni++) {
                int nj = ni >> 1;
                if (ni & 1)
                    mma16816(acc[mi][ni], a[mi][0], a[mi][1], a[mi][2], a[mi][3],
                             bb[nj][2], bb[nj][3]);
                else
                    mma16816(acc[mi][ni], a[mi][0], a[mi][1], a[mi][2], a[mi][3],
                             bb[nj][0], bb[nj][1]);
            }
    }

    int rbase = lane >> 2;
    int cbase = (lane & 3)*2;
    float lsum = 0.f, lsq = 0.f;
    #pragma unroll
    for (int mi = 0; mi < 2; mi++) {
        int row = wm*32 + mi*16 + rbase;
        float q2a = q2s[row], q2b = q2s[row + 8];
        float* r0p = co + ((size_t)(bh*Ln + bi0 + row))*Ln + bj0;
        float* r1p = r0p + 8*Ln;
        #pragma unroll
        for (int ni = 0; ni < 8; ni++) {
            int col = wn*64 + ni*8 + cbase;
            float k0 = k2s[col], k1 = k2s[col + 1];
            float2 s0, s1;
            s0.x = 2.f*acc[mi][ni][0] - q2a - k0;
            s0.y = 2.f*acc[mi][ni][1] - q2a - k1;
            s1.x = 2.f*acc[mi][ni][2] - q2b - k0;
            s1.y = 2.f*acc[mi][ni][3] - q2b - k1;
            *(float2*)(r0p + col) = s0;
            *(float2*)(r1p + col) = s1;
            lsum += s0.x + s0.y + s1.x + s1.y;
            lsq  += s0.x*s0.x + s0.y*s0.y + s1.x*s1.x + s1.y*s1.y;
        }
    }
    double ds = (double)lsum, dq = (double)lsq;
    #pragma unroll
    for (int o = 16; o; o >>= 1) {
        ds += __shfl_xor_sync(0xffffffffu, ds, o);
        dq += __shfl_xor_sync(0xffffffffu, dq, o);
    }
    if (lane == 0) { rs[warp] = ds; rq[warp] = dq; }
    __syncthreads();
    if (tid == 0) {
        atomicAdd(&g_sum1[h], rs[0]+rs[1]+rs[2]+rs[3]+rs[4]+rs[5]+rs[6]+rs[7]);
        atomicAdd(&g_sumsq1[h], rq[0]+rq[1]+rq[2]+rq[3]+rq[4]+rq[5]+rq[6]+rq[7]);
    }
}

// ---------------- softmax: stats1 inline + in-place softmax + column partials ----------------
__global__ void __launch_bounds__(512) softmax_kernel(float* __restrict__ co,
                                                      const float* __restrict__ g1,
                                                      const float* __restrict__ b1) {
    extern __shared__ char sm[];
    float (*red)[Ln] = (float(*)[Ln])sm;            // 16 x 1024 floats
    unsigned char* sval = (unsigned char*)(sm + 16*Ln*4);
    __shared__ float ssc[2];
    int bh = blockIdx.x >> 6;
    int rb = blockIdx.x & 63;
    int b = bh / Hn, h = bh % Hn;
    int tid = threadIdx.x, warp = tid >> 5, lane = tid & 31;
    for (int j = tid; j < Ln; j += 512) sval[j] = g_valid[b*Ln + j];
    if (tid == 0) {
        double n = (double)Bn*Ln*Ln;
        double m = g_sum1[h]/n;
        double var = g_sumsq1[h]/n - m*m;
        float rstd = (float)rsqrt(var + (double)EPSf);
        ssc[0] = g1[h]*rstd;
        ssc[1] = b1[h] - (float)m*rstd*g1[h];
    }
    __syncthreads();

    int i = rb*16 + warp;
    bool rowvalid = sval[i] != 0;
    float scale = ssc[0], shift = ssc[1];
    float4* Sr = (float4*)(co + ((size_t)bh*Ln + i)*Ln);

    float v[32];
    float sum = 0.f;
    #pragma unroll
    for (int c = 0; c < 8; c++) {
        float4 x = Sr[c*32 + lane];
        int j0 = c*128 + lane*4;
        float e0 = (rowvalid && sval[j0+0]) ? __expf(x.x*scale + shift) : 1.f;
        float e1 = (rowvalid && sval[j0+1]) ? __expf(x.y*scale + shift) : 1.f;
        float e2 = (rowvalid && sval[j0+2]) ? __expf(x.z*scale + shift) : 1.f;
        float e3 = (rowvalid && sval[j0+3]) ? __expf(x.w*scale + shift) : 1.f;
        v[c*4+0]=e0; v[c*4+1]=e1; v[c*4+2]=e2; v[c*4+3]=e3;
        sum += e0 + e1 + e2 + e3;
    }
    #pragma unroll
    for (int o = 16; o; o >>= 1) sum += __shfl_xor_sync(0xffffffffu, sum, o);
    float inv = 1.0f / sum;

    #pragma unroll
    for (int c = 0; c < 8; c++) {
        int j0 = c*128 + lane*4;
        float4 o4;
        o4.x = v[c*4+0]*inv; o4.y = v[c*4+1]*inv;
        o4.z = v[c*4+2]*inv; o4.w = v[c*4+3]*inv;
        Sr[c*32 + lane] = o4;
        *(float4*)&red[warp][j0] = o4;
    }
    __syncthreads();

    if (tid < 256) {
        int j = tid*4;
        float4 a = *(float4*)&red[0][j];
        #pragma unroll
        for (int w = 1; w < 16; w++) {
            float4 x = *(float4*)&red[w][j];
            a.x += x.x; a.y += x.y; a.z += x.z; a.w += x.w;
        }
        atomicAdd(&g_w[bh*Ln + j + 0], a.x);
        atomicAdd(&g_w[bh*Ln + j + 1], a.y);
        atomicAdd(&g_w[bh*Ln + j + 2], a.z);
        atomicAdd(&g_w[bh*Ln + j + 3], a.w);
    }
}

// ---------------- tail: stats2 (redundant per block) + gate + final softmax; 1 block/batch ----------------
__global__ void __launch_bounds__(1024) tail_kernel(const float* __restrict__ g2,
                                                    const float* __restrict__ b2,
                                                    const float* __restrict__ Wp,
                                                    const float* __restrict__ bp,
                                                    float* __restrict__ out) {
    __shared__ float s_scale2[Hn], s_shift2[Hn];
    __shared__ double rsd[32], rqd[32];
    __shared__ float redd[32], bcast[2];
    int bb = blockIdx.x;
    int tid = threadIdx.x, warp = tid >> 5, lane = tid & 31;

    // stats2 for all heads (each block redundantly)
    for (int h = 0; h < Hn; h++) {
        float ls = 0.f, lq = 0.f;
        #pragma unroll
        for (int b = 0; b < Bn; b++) {
            float x = g_w[(b*Hn + h)*Ln + tid];
            ls += x; lq += x*x;
        }
        double ds = (double)ls, dq = (double)lq;
        #pragma unroll
        for (int o = 16; o; o >>= 1) {
            ds += __shfl_xor_sync(0xffffffffu, ds, o);
            dq += __shfl_xor_sync(0xffffffffu, dq, o);
        }
        if (lane == 0) { rsd[warp] = ds; rqd[warp] = dq; }
        __syncthreads();
        if (tid == 0) {
            double S = 0.0, Q2 = 0.0;
            for (int w = 0; w < 32; w++) { S += rsd[w]; Q2 += rqd[w]; }
            double n = (double)Bn*Ln;
            double m = S/n;
            double var = Q2/n - m*m;
            float rstd = (float)rsqrt(var + (double)EPSf);
            s_scale2[h] = g2[h]*rstd;
            s_shift2[h] = b2[h] - (float)m*rstd*g2[h];
        }
        __syncthreads();
    }

    // gate for this batch
    int l = tid;
    float z0 = bp[0], z1 = bp[1];
    #pragma unroll
    for (int h = 0; h < Hn; h++) {
        float wn = g_w[(bb*Hn + h)*Ln + l]*s_scale2[h] + s_shift2[h];
        z0 += Wp[h]      * wn;
        z1 += Wp[Hn + h] * wn;
    }
    const float NEG_INF = __int_as_float(0xff800000);
    float p = 1.f/(1.f + __expf(z1 - z0));
    float x = g_valid[bb*Ln + l] ? p : NEG_INF;

    // final softmax over L
    float m = x;
    #pragma unroll
    for (int o = 16; o; o >>= 1) m = fmaxf(m, __shfl_xor_sync(0xffffffffu, m, o));
    if (lane == 0) redd[warp] = m;
    __syncthreads();
    if (warp == 0) {
        float mm = redd[lane];
        #pragma unroll
        for (int o = 16; o; o >>= 1) mm = fmaxf(mm, __shfl_xor_sync(0xffffffffu, mm, o));
        if (lane == 0) bcast[0] = mm;
    }
    __syncthreads();
    float e = __expf(x - bcast[0]);
    float s = e;
    #pragma unroll
    for (int o = 16; o; o >>= 1) s += __shfl_xor_sync(0xffffffffu, s, o);
    __syncthreads();
    if (lane == 0) redd[warp] = s;
    __syncthreads();
    if (warp == 0) {
        float ss = redd[lane];
        #pragma unroll
        for (int o = 16; o; o >>= 1) ss += __shfl_xor_sync(0xffffffffu, ss, o);
        if (lane == 0) bcast[1] = ss;
    }
    __syncthreads();
    out[OFF_W + bb*Ln + l] = e / bcast[1];
}

// ---------------- launch ----------------
extern "C" void kernel_launch(void* const* d_in, const int* in_sizes, int n_in,
                              void* d_out, int out_size) {
    const float* Q  = (const float*)d_in[0];
    const float* K  = (const float*)d_in[1];
    const float* V  = (const float*)d_in[2];
    const unsigned int* bx = (const unsigned int*)d_in[4];
    const float* g1 = (const float*)d_in[5];
    const float* b1 = (const float*)d_in[6];
    const float* g2 = (const float*)d_in[7];
    const float* b2 = (const float*)d_in[8];
    const float* Wp = (const float*)d_in[9];
    const float* bp = (const float*)d_in[10];
    float* out = (float*)d_out;

    const int SMG = 2*128*GLDH*2;        // 69632
    const int SMS = 16*Ln*4 + Ln;        // 66560
    cudaFuncSetAttribute(gemm_kernel, cudaFuncAttributeMaxDynamicSharedMemorySize, SMG);
    cudaFuncSetAttribute(softmax_kernel, cudaFuncAttributeMaxDynamicSharedMemorySize, SMS);

    sq_kernel<<<1024 + 97, 256>>>(Q, K, bx);
    vout_kernel<<<(BHn*Ln*DHn/4 + 255)/256, 256>>>(V, out);
    gemm_kernel<<<dim3(Ln/128, Ln/128, BHn), 256, SMG>>>(Q, K, out);
    softmax_kernel<<<BHn*64, 512, SMS>>>(out, g1, b1);
    tail_kernel<<<Bn, 1024>>>(g2, b2, Wp, bp, out);
}

// round 15
// speedup vs baseline: 1.0529x; 1.0529x over previous
#include <cuda_runtime.h>
#include <cuda_fp16.h>
#include <cstdint>

#define Bn  4
#define Ln  1024
#define Dn  768
#define Hn  6
#define DHn 128
#define BHn (Bn*Hn)
#define EPSf 1e-5f
#define GLDH 136   /* half leading dim: 128 + 8 */

#define OFF_CO 0
#define OFF_W  (BHn*Ln*Ln)          /* 25165824 */
#define OFF_V  (OFF_W + Bn*Ln)      /* 25169920 */

// ---------------- scratch ----------------
__device__ float  g_q2[BHn*Ln];
__device__ float  g_k2[BHn*Ln];
__device__ double g_sum1[Hn];
__device__ double g_sumsq1[Hn];
__device__ float  g_w[BHn*Ln];
__device__ unsigned char g_valid[Bn*Ln];

// ---------------- PTX: ldmatrix + mma ----------------
__device__ __forceinline__ void ldsm_x4(uint32_t& r0, uint32_t& r1, uint32_t& r2, uint32_t& r3,
                                        uint32_t addr) {
    asm volatile("ldmatrix.sync.aligned.m8n8.x4.shared.b16 {%0,%1,%2,%3}, [%4];"
                 : "=r"(r0), "=r"(r1), "=r"(r2), "=r"(r3) : "r"(addr));
}
__device__ __forceinline__ void mma16816(float* c, uint32_t a0, uint32_t a1, uint32_t a2,
                                         uint32_t a3, uint32_t b0, uint32_t b1) {
    asm volatile("mma.sync.aligned.m16n8k16.row.col.f32.f16.f16.f32 "
                 "{%0,%1,%2,%3}, {%4,%5,%6,%7}, {%8,%9}, {%0,%1,%2,%3};"
                 : "+f"(c[0]), "+f"(c[1]), "+f"(c[2]), "+f"(c[3])
                 : "r"(a0), "r"(a1), "r"(a2), "r"(a3), "r"(b0), "r"(b1));
}
__device__ __forceinline__ uint32_t smem_u32(const void* p) {
    return (uint32_t)__cvta_generic_to_shared(p);
}

// ---------------- sq + prep fused ----------------
__global__ void sq_kernel(const float* __restrict__ Q, const float* __restrict__ K,
                          const unsigned int* __restrict__ w) {
    if (blockIdx.x >= 1024) {
        int bidx = blockIdx.x - 1024;
        if (bidx < 96) {
            int idx = bidx*256 + threadIdx.x;
            g_w[idx] = 0.f;
            if (idx < Hn) { g_sum1[idx] = 0.0; g_sumsq1[idx] = 0.0; }
            return;
        }
        __shared__ int s_float, s_byte;
        if (threadIdx.x == 0) { s_float = 0; s_byte = 0; }
        __syncthreads();
        for (int i = threadIdx.x; i < (Bn*Ln)/4; i += blockDim.x) {
            unsigned v = w[i];
            if (v == 0x3f800000u) atomicOr(&s_float, 1);
            else if (v > 1u)      atomicOr(&s_byte, 1);
        }
        __syncthreads();
        int byte_mode = (!s_float) && s_byte;
        const unsigned char* bytes = (const unsigned char*)w;
        for (int i = threadIdx.x; i < Bn*Ln; i += blockDim.x) {
            bool padded = byte_mode ? (bytes[i] != 0) : (w[i] != 0u);
            g_valid[i] = padded ? 0 : 1;
        }
        return;
    }
    int gw = (blockIdx.x*blockDim.x + threadIdx.x) >> 5;
    int lane = threadIdx.x & 31;
    int t = gw / (Bn*Ln);
    int r = gw % (Bn*Ln);
    const float* src = (t ? K : Q) + (size_t)r*Dn;
    float* dst = t ? g_k2 : g_q2;
    int b = r >> 10, l = r & (Ln-1);
    float4 x[Hn];
    #pragma unroll
    for (int hh = 0; hh < Hn; hh++) x[hh] = ((const float4*)src)[hh*32 + lane];
    #pragma unroll
    for (int hh = 0; hh < Hn; hh++) {
        float s = x[hh].x*x[hh].x + x[hh].y*x[hh].y + x[hh].z*x[hh].z + x[hh].w*x[hh].w;
        #pragma unroll
        for (int o = 16; o; o >>= 1) s += __shfl_xor_sync(0xffffffffu, s, o);
        if (lane == 0) dst[(b*Hn + hh)*Ln + l] = s;
    }
}

// ---------------- Vh output: transpose copy ----------------
__global__ void vout_kernel(const float* __restrict__ V, float* __restrict__ out) {
    int idx = blockIdx.x*blockDim.x + threadIdx.x;
    if (idx >= BHn*Ln*DHn/4) return;
    int d4 = idx & 31;
    int l  = (idx >> 5) & (Ln-1);
    int h  = (idx >> 15) % Hn;
    int b  = idx / (32*Ln*Hn);
    float4 v = *(const float4*)(V + ((size_t)(b*Ln + l))*Dn + h*DHn + d4*4);
    ((float4*)(out + OFF_V))[idx] = v;
}

// ---------------- main GEMM (raw mma, R11 config): CTA 128x128, 128 thr, warp 64x64 ----------------
__global__ void __launch_bounds__(128, 2) gemm_kernel(const float* __restrict__ Q,
                                                      const float* __restrict__ K,
                                                      float* __restrict__ co) {
    extern __shared__ char smraw[];
    __half* As = (__half*)smraw;                    // 128 x GLDH
    __half* Bs = As + 128*GLDH;
    __shared__ float q2s[128], k2s[128];
    __shared__ double rs[4], rq[4];

    int bh = blockIdx.z; int b = bh / Hn, h = bh % Hn;
    int bi0 = blockIdx.y*128, bj0 = blockIdx.x*128;
    const float* Qb = Q + (size_t)b*Ln*Dn + h*DHn;
    const float* Kb = K + (size_t)b*Ln*Dn + h*DHn;
    int tid = threadIdx.x, warp = tid >> 5, lane = tid & 31;

    q2s[tid] = g_q2[bh*Ln + bi0 + tid];
    k2s[tid] = g_k2[bh*Ln + bj0 + tid];

    #pragma unroll
    for (int i = 0; i < 32; i++) {
        int t = tid + i*128;
        int r = t >> 5, c = t & 31;
        float4 q = *(const float4*)(Qb + (size_t)(bi0 + r)*Dn + c*4);
        *(half2*)&As[r*GLDH + c*4 + 0] = __floats2half2_rn(q.x, q.y);
        *(half2*)&As[r*GLDH + c*4 + 2] = __floats2half2_rn(q.z, q.w);
    }
    #pragma unroll
    for (int i = 0; i < 32; i++) {
        int t = tid + i*128;
        int r = t >> 5, c = t & 31;
        float4 k = *(const float4*)(Kb + (size_t)(bj0 + r)*Dn + c*4);
        *(half2*)&Bs[r*GLDH + c*4 + 0] = __floats2half2_rn(k.x, k.y);
        *(half2*)&Bs[r*GLDH + c*4 + 2] = __floats2half2_rn(k.z, k.w);
    }
    __syncthreads();

    int wm = warp & 1, wn = warp >> 1;
    uint32_t aBase = smem_u32(As) +
        (uint32_t)(((wm*64 + (lane & 15))*GLDH + (lane >> 4)*8) * 2);
    uint32_t bBase = smem_u32(Bs) +
        (uint32_t)(((wn*64 + (lane & 7) + ((lane >> 4) << 3))*GLDH + ((lane >> 3) & 1)*8) * 2);

    float acc[4][8][4];
    #pragma unroll
    for (int mi = 0; mi < 4; mi++)
        #pragma unroll
        for (int ni = 0; ni < 8; ni++)
            #pragma unroll
            for (int e = 0; e < 4; e++) acc[mi][ni][e] = 0.f;

    #pragma unroll
    for (int k = 0; k < 128; k += 16) {
        uint32_t a[4][4], bb[4][4];
        #pragma unroll
        for (int mi = 0; mi < 4; mi++)
            ldsm_x4(a[mi][0], a[mi][1], a[mi][2], a[mi][3],
                    aBase + (uint32_t)((mi*16*GLDH + k)*2));
        #pragma unroll
        for (int nj = 0; nj < 4; nj++)
            ldsm_x4(bb[nj][0], bb[nj][1], bb[nj][2], bb[nj][3],
                    bBase + (uint32_t)((nj*16*GLDH + k)*2));
        #pragma unroll
        for (int mi = 0; mi < 4; mi++)
            #pragma unroll
            for (int ni = 0; ni < 8; ni++) {
                int nj = ni >> 1;
                if (ni & 1)
                    mma16816(acc[mi][ni], a[mi][0], a[mi][1], a[mi][2], a[mi][3],
                             bb[nj][2], bb[nj][3]);
                else
                    mma16816(acc[mi][ni], a[mi][0], a[mi][1], a[mi][2], a[mi][3],
                             bb[nj][0], bb[nj][1]);
            }
    }

    int rbase = lane >> 2;
    int cbase = (lane & 3)*2;
    float lsum = 0.f, lsq = 0.f;
    #pragma unroll
    for (int mi = 0; mi < 4; mi++) {
        int row = wm*64 + mi*16 + rbase;
        float q2a = q2s[row], q2b = q2s[row + 8];
        float* r0p = co + ((size_t)(bh*Ln + bi0 + row))*Ln + bj0;
        float* r1p = r0p + 8*Ln;
        #pragma unroll
        for (int ni = 0; ni < 8; ni++) {
            int col = wn*64 + ni*8 + cbase;
            float k0 = k2s[col], k1 = k2s[col + 1];
            float2 s0, s1;
            s0.x = 2.f*acc[mi][ni][0] - q2a - k0;
            s0.y = 2.f*acc[mi][ni][1] - q2a - k1;
            s1.x = 2.f*acc[mi][ni][2] - q2b - k0;
            s1.y = 2.f*acc[mi][ni][3] - q2b - k1;
            *(float2*)(r0p + col) = s0;
            *(float2*)(r1p + col) = s1;
            lsum += s0.x + s0.y + s1.x + s1.y;
            lsq  += s0.x*s0.x + s0.y*s0.y + s1.x*s1.x + s1.y*s1.y;
        }
    }
    double ds = (double)lsum, dq = (double)lsq;
    #pragma unroll
    for (int o = 16; o; o >>= 1) {
        ds += __shfl_xor_sync(0xffffffffu, ds, o);
        dq += __shfl_xor_sync(0xffffffffu, dq, o);
    }
    if (lane == 0) { rs[warp] = ds; rq[warp] = dq; }
    __syncthreads();
    if (tid == 0) {
        atomicAdd(&g_sum1[h], rs[0]+rs[1]+rs[2]+rs[3]);
        atomicAdd(&g_sumsq1[h], rq[0]+rq[1]+rq[2]+rq[3]);
    }
}

// ---------------- softmax: stats1 inline + in-place softmax + column partials ----------------
__global__ void __launch_bounds__(512) softmax_kernel(float* __restrict__ co,
                                                      const float* __restrict__ g1,
                                                      const float* __restrict__ b1) {
    extern __shared__ char sm[];
    float (*red)[Ln] = (float(*)[Ln])sm;            // 16 x 1024 floats
    unsigned char* sval = (unsigned char*)(sm + 16*Ln*4);
    __shared__ float ssc[2];
    int bh = blockIdx.x >> 6;
    int rb = blockIdx.x & 63;
    int b = bh / Hn, h = bh % Hn;
    int tid = threadIdx.x, warp = tid >> 5, lane = tid & 31;
    for (int j = tid; j < Ln; j += 512) sval[j] = g_valid[b*Ln + j];
    if (tid == 0) {
        double n = (double)Bn*Ln*Ln;
        double m = g_sum1[h]/n;
        double var = g_sumsq1[h]/n - m*m;
        float rstd = (float)rsqrt(var + (double)EPSf);
        ssc[0] = g1[h]*rstd;
        ssc[1] = b1[h] - (float)m*rstd*g1[h];
    }
    __syncthreads();

    int i = rb*16 + warp;
    bool rowvalid = sval[i] != 0;
    float scale = ssc[0], shift = ssc[1];
    float4* Sr = (float4*)(co + ((size_t)bh*Ln + i)*Ln);

    float v[32];
    float sum = 0.f;
    #pragma unroll
    for (int c = 0; c < 8; c++) {
        float4 x = Sr[c*32 + lane];
        int j0 = c*128 + lane*4;
        float e0 = (rowvalid && sval[j0+0]) ? __expf(x.x*scale + shift) : 1.f;
        float e1 = (rowvalid && sval[j0+1]) ? __expf(x.y*scale + shift) : 1.f;
        float e2 = (rowvalid && sval[j0+2]) ? __expf(x.z*scale + shift) : 1.f;
        float e3 = (rowvalid && sval[j0+3]) ? __expf(x.w*scale + shift) : 1.f;
        v[c*4+0]=e0; v[c*4+1]=e1; v[c*4+2]=e2; v[c*4+3]=e3;
        sum += e0 + e1 + e2 + e3;
    }
    #pragma unroll
    for (int o = 16; o; o >>= 1) sum += __shfl_xor_sync(0xffffffffu, sum, o);
    float inv = 1.0f / sum;

    #pragma unroll
    for (int c = 0; c < 8; c++) {
        int j0 = c*128 + lane*4;
        float4 o4;
        o4.x = v[c*4+0]*inv; o4.y = v[c*4+1]*inv;
        o4.z = v[c*4+2]*inv; o4.w = v[c*4+3]*inv;
        Sr[c*32 + lane] = o4;
        *(float4*)&red[warp][j0] = o4;
    }
    __syncthreads();

    if (tid < 256) {
        int j = tid*4;
        float4 a = *(float4*)&red[0][j];
        #pragma unroll
        for (int w = 1; w < 16; w++) {
            float4 x = *(float4*)&red[w][j];
            a.x += x.x; a.y += x.y; a.z += x.z; a.w += x.w;
        }
        atomicAdd(&g_w[bh*Ln + j + 0], a.x);
        atomicAdd(&g_w[bh*Ln + j + 1], a.y);
        atomicAdd(&g_w[bh*Ln + j + 2], a.z);
        atomicAdd(&g_w[bh*Ln + j + 3], a.w);
    }
}

// ---------------- tail: stats2 (redundant per block) + gate + final softmax; 1 block/batch ----------------
__global__ void __launch_bounds__(1024) tail_kernel(const float* __restrict__ g2,
                                                    const float* __restrict__ b2,
                                                    const float* __restrict__ Wp,
                                                    const float* __restrict__ bp,
                                                    float* __restrict__ out) {
    __shared__ float s_scale2[Hn], s_shift2[Hn];
    __shared__ double rsd[32], rqd[32];
    __shared__ float redd[32], bcast[2];
    int bb = blockIdx.x;
    int tid = threadIdx.x, warp = tid >> 5, lane = tid & 31;

    for (int h = 0; h < Hn; h++) {
        float ls = 0.f, lq = 0.f;
        #pragma unroll
        for (int b = 0; b < Bn; b++) {
            float x = g_w[(b*Hn + h)*Ln + tid];
            ls += x; lq += x*x;
        }
        double ds = (double)ls, dq = (double)lq;
        #pragma unroll
        for (int o = 16; o; o >>= 1) {
            ds += __shfl_xor_sync(0xffffffffu, ds, o);
            dq += __shfl_xor_sync(0xffffffffu, dq, o);
        }
        if (lane == 0) { rsd[warp] = ds; rqd[warp] = dq; }
        __syncthreads();
        if (tid == 0) {
            double S = 0.0, Q2 = 0.0;
            for (int w = 0; w < 32; w++) { S += rsd[w]; Q2 += rqd[w]; }
            double n = (double)Bn*Ln;
            double m = S/n;
            double var = Q2/n - m*m;
            float rstd = (float)rsqrt(var + (double)EPSf);
            s_scale2[h] = g2[h]*rstd;
            s_shift2[h] = b2[h] - (float)m*rstd*g2[h];
        }
        __syncthreads();
    }

    int l = tid;
    float z0 = bp[0], z1 = bp[1];
    #pragma unroll
    for (int h = 0; h < Hn; h++) {
        float wn = g_w[(bb*Hn + h)*Ln + l]*s_scale2[h] + s_shift2[h];
        z0 += Wp[h]      * wn;
        z1 += Wp[Hn + h] * wn;
    }
    const float NEG_INF = __int_as_float(0xff800000);
    float p = 1.f/(1.f + __expf(z1 - z0));
    float x = g_valid[bb*Ln + l] ? p : NEG_INF;

    float m = x;
    #pragma unroll
    for (int o = 16; o; o >>= 1) m = fmaxf(m, __shfl_xor_sync(0xffffffffu, m, o));
    if (lane == 0) redd[warp] = m;
    __syncthreads();
    if (warp == 0) {
        float mm = redd[lane];
        #pragma unroll
        for (int o = 16; o; o >>= 1) mm = fmaxf(mm, __shfl_xor_sync(0xffffffffu, mm, o));
        if (lane == 0) bcast[0] = mm;
    }
    __syncthreads();
    float e = __expf(x - bcast[0]);
    float s = e;
    #pragma unroll
    for (int o = 16; o; o >>= 1) s += __shfl_xor_sync(0xffffffffu, s, o);
    __syncthreads();
    if (lane == 0) redd[warp] = s;
    __syncthreads();
    if (warp == 0) {
        float ss = redd[lane];
        #pragma unroll
        for (int o = 16; o; o >>= 1) ss += __shfl_xor_sync(0xffffffffu, ss, o);
        if (lane == 0) bcast[1] = ss;
    }
    __syncthreads();
    out[OFF_W + bb*Ln + l] = e / bcast[1];
}

// ---------------- launch ----------------
extern "C" void kernel_launch(void* const* d_in, const int* in_sizes, int n_in,
                              void* d_out, int out_size) {
    const float* Q  = (const float*)d_in[0];
    const float* K  = (const float*)d_in[1];
    const float* V  = (const float*)d_in[2];
    const unsigned int* bx = (const unsigned int*)d_in[4];
    const float* g1 = (const float*)d_in[5];
    const float* b1 = (const float*)d_in[6];
    const float* g2 = (const float*)d_in[7];
    const float* b2 = (const float*)d_in[8];
    const float* Wp = (const float*)d_in[9];
    const float* bp = (const float*)d_in[10];
    float* out = (float*)d_out;

    const int SMG = 2*128*GLDH*2;        // 69632
    const int SMS = 16*Ln*4 + Ln;        // 66560
    cudaFuncSetAttribute(gemm_kernel, cudaFuncAttributeMaxDynamicSharedMemorySize, SMG);
    cudaFuncSetAttribute(softmax_kernel, cudaFuncAttributeMaxDynamicSharedMemorySize, SMS);

    sq_kernel<<<1024 + 97, 256>>>(Q, K, bx);
    vout_kernel<<<(BHn*Ln*DHn/4 + 255)/256, 256>>>(V, out);
    gemm_kernel<<<dim3(Ln/128, Ln/128, BHn), 128, SMG>>>(Q, K, out);
    softmax_kernel<<<BHn*64, 512, SMS>>>(out, g1, b1);
    tail_kernel<<<Bn, 1024>>>(g2, b2, Wp, bp, out);
}

// round 16
// speedup vs baseline: 1.3118x; 1.2459x over previous
#include <cuda_runtime.h>
#include <cuda_fp16.h>
#include <cstdint>

#define Bn  4
#define Ln  1024
#define Dn  768
#define Hn  6
#define DHn 128
#define BHn (Bn*Hn)
#define EPSf 1e-5f
#define GLDH 136   /* half leading dim: 128 + 8 */

#define OFF_CO 0
#define OFF_W  (BHn*Ln*Ln)          /* 25165824 */
#define OFF_V  (OFF_W + Bn*Ln)      /* 25169920 */

// ---------------- scratch ----------------
__device__ float  g_q2[BHn*Ln];
__device__ float  g_k2[BHn*Ln];
__device__ double g_sum1[Hn];
__device__ double g_sumsq1[Hn];
__device__ float  g_scale1[Hn];
__device__ float  g_shift1[Hn];
__device__ float  g_w[BHn*Ln];
__device__ float  g_scale2[Hn];
__device__ float  g_shift2[Hn];
__device__ float  g_p[Bn*Ln];
__device__ unsigned char g_valid[Bn*Ln];

// ---------------- PTX: ldmatrix + mma ----------------
__device__ __forceinline__ void ldsm_x4(uint32_t& r0, uint32_t& r1, uint32_t& r2, uint32_t& r3,
                                        uint32_t addr) {
    asm volatile("ldmatrix.sync.aligned.m8n8.x4.shared.b16 {%0,%1,%2,%3}, [%4];"
                 : "=r"(r0), "=r"(r1), "=r"(r2), "=r"(r3) : "r"(addr));
}
__device__ __forceinline__ void mma16816(float* c, uint32_t a0, uint32_t a1, uint32_t a2,
                                         uint32_t a3, uint32_t b0, uint32_t b1) {
    asm volatile("mma.sync.aligned.m16n8k16.row.col.f32.f16.f16.f32 "
                 "{%0,%1,%2,%3}, {%4,%5,%6,%7}, {%8,%9}, {%0,%1,%2,%3};"
                 : "+f"(c[0]), "+f"(c[1]), "+f"(c[2]), "+f"(c[3])
                 : "r"(a0), "r"(a1), "r"(a2), "r"(a3), "r"(b0), "r"(b1));
}
__device__ __forceinline__ uint32_t smem_u32(const void* p) {
    return (uint32_t)__cvta_generic_to_shared(p);
}

// ---------------- sq + prep fused ----------------
__global__ void sq_kernel(const float* __restrict__ Q, const float* __restrict__ K,
                          const unsigned int* __restrict__ w) {
    if (blockIdx.x >= 1024) {
        int bidx = blockIdx.x - 1024;
        if (bidx < 96) {
            int idx = bidx*256 + threadIdx.x;
            g_w[idx] = 0.f;
            if (idx < Hn) { g_sum1[idx] = 0.0; g_sumsq1[idx] = 0.0; }
            return;
        }
        __shared__ int s_float, s_byte;
        if (threadIdx.x == 0) { s_float = 0; s_byte = 0; }
        __syncthreads();
        for (int i = threadIdx.x; i < (Bn*Ln)/4; i += blockDim.x) {
            unsigned v = w[i];
            if (v == 0x3f800000u) atomicOr(&s_float, 1);
            else if (v > 1u)      atomicOr(&s_byte, 1);
        }
        __syncthreads();
        int byte_mode = (!s_float) && s_byte;
        const unsigned char* bytes = (const unsigned char*)w;
        for (int i = threadIdx.x; i < Bn*Ln; i += blockDim.x) {
            bool padded = byte_mode ? (bytes[i] != 0) : (w[i] != 0u);
            g_valid[i] = padded ? 0 : 1;
        }
        return;
    }
    int gw = (blockIdx.x*blockDim.x + threadIdx.x) >> 5;
    int lane = threadIdx.x & 31;
    int t = gw / (Bn*Ln);
    int r = gw % (Bn*Ln);
    const float* src = (t ? K : Q) + (size_t)r*Dn;
    float* dst = t ? g_k2 : g_q2;
    int b = r >> 10, l = r & (Ln-1);
    float4 x[Hn];
    #pragma unroll
    for (int hh = 0; hh < Hn; hh++) x[hh] = ((const float4*)src)[hh*32 + lane];
    #pragma unroll
    for (int hh = 0; hh < Hn; hh++) {
        float s = x[hh].x*x[hh].x + x[hh].y*x[hh].y + x[hh].z*x[hh].z + x[hh].w*x[hh].w;
        #pragma unroll
        for (int o = 16; o; o >>= 1) s += __shfl_xor_sync(0xffffffffu, s, o);
        if (lane == 0) dst[(b*Hn + hh)*Ln + l] = s;
    }
}

// ---------------- Vh output: transpose copy ----------------
__global__ void vout_kernel(const float* __restrict__ V, float* __restrict__ out) {
    int idx = blockIdx.x*blockDim.x + threadIdx.x;
    if (idx >= BHn*Ln*DHn/4) return;
    int d4 = idx & 31;
    int l  = (idx >> 5) & (Ln-1);
    int h  = (idx >> 15) % Hn;
    int b  = idx / (32*Ln*Hn);
    float4 v = *(const float4*)(V + ((size_t)(b*Ln + l))*Dn + h*DHn + d4*4);
    ((float4*)(out + OFF_V))[idx] = v;
}

// ---------------- main GEMM (raw mma): S = 2QK^T - q2 - k2 -> co, + BN1 stats ----------------
// CTA 128x128, 128 threads, warp tile 64x64 (2x2), register epilogue (no staging).
__global__ void __launch_bounds__(128, 2) gemm_kernel(const float* __restrict__ Q,
                                                      const float* __restrict__ K,
                                                      float* __restrict__ co) {
    extern __shared__ char smraw[];
    __half* As = (__half*)smraw;                    // 128 x GLDH
    __half* Bs = As + 128*GLDH;
    __shared__ float q2s[128], k2s[128];
    __shared__ double rs[4], rq[4];

    int bh = blockIdx.z; int b = bh / Hn, h = bh % Hn;
    int bi0 = blockIdx.y*128, bj0 = blockIdx.x*128;
    const float* Qb = Q + (size_t)b*Ln*Dn + h*DHn;
    const float* Kb = K + (size_t)b*Ln*Dn + h*DHn;
    int tid = threadIdx.x, warp = tid >> 5, lane = tid & 31;

    q2s[tid] = g_q2[bh*Ln + bi0 + tid];
    k2s[tid] = g_k2[bh*Ln + bj0 + tid];

    #pragma unroll
    for (int i = 0; i < 32; i++) {
        int t = tid + i*128;
        int r = t >> 5, c = t & 31;
        float4 q = *(const float4*)(Qb + (size_t)(bi0 + r)*Dn + c*4);
        *(half2*)&As[r*GLDH + c*4 + 0] = __floats2half2_rn(q.x, q.y);
        *(half2*)&As[r*GLDH + c*4 + 2] = __floats2half2_rn(q.z, q.w);
    }
    #pragma unroll
    for (int i = 0; i < 32; i++) {
        int t = tid + i*128;
        int r = t >> 5, c = t & 31;
        float4 k = *(const float4*)(Kb + (size_t)(bj0 + r)*Dn + c*4);
        *(half2*)&Bs[r*GLDH + c*4 + 0] = __floats2half2_rn(k.x, k.y);
        *(half2*)&Bs[r*GLDH + c*4 + 2] = __floats2half2_rn(k.z, k.w);
    }
    __syncthreads();

    int wm = warp & 1, wn = warp >> 1;
    uint32_t aBase = smem_u32(As) +
        (uint32_t)(((wm*64 + (lane & 15))*GLDH + (lane >> 4)*8) * 2);
    uint32_t bBase = smem_u32(Bs) +
        (uint32_t)(((wn*64 + (lane & 7) + ((lane >> 4) << 3))*GLDH + ((lane >> 3) & 1)*8) * 2);

    float acc[4][8][4];
    #pragma unroll
    for (int mi = 0; mi < 4; mi++)
        #pragma unroll
        for (int ni = 0; ni < 8; ni++)
            #pragma unroll
            for (int e = 0; e < 4; e++) acc[mi][ni][e] = 0.f;

    #pragma unroll
    for (int k = 0; k < 128; k += 16) {
        uint32_t a[4][4], bb[4][4];
        #pragma unroll
        for (int mi = 0; mi < 4; mi++)
            ldsm_x4(a[mi][0], a[mi][1], a[mi][2], a[mi][3],
                    aBase + (uint32_t)((mi*16*GLDH + k)*2));
        #pragma unroll
        for (int nj = 0; nj < 4; nj++)
            ldsm_x4(bb[nj][0], bb[nj][1], bb[nj][2], bb[nj][3],
                    bBase + (uint32_t)((nj*16*GLDH + k)*2));
        #pragma unroll
        for (int mi = 0; mi < 4; mi++)
            #pragma unroll
            for (int ni = 0; ni < 8; ni++) {
                int nj = ni >> 1;
                if (ni & 1)
                    mma16816(acc[mi][ni], a[mi][0], a[mi][1], a[mi][2], a[mi][3],
                             bb[nj][2], bb[nj][3]);
                else
                    mma16816(acc[mi][ni], a[mi][0], a[mi][1], a[mi][2], a[mi][3],
                             bb[nj][0], bb[nj][1]);
            }
    }

    int rbase = lane >> 2;
    int cbase = (lane & 3)*2;
    float lsum = 0.f, lsq = 0.f;
    #pragma unroll
    for (int mi = 0; mi < 4; mi++) {
        int row = wm*64 + mi*16 + rbase;
        float q2a = q2s[row], q2b = q2s[row + 8];
        float* r0p = co + ((size_t)(bh*Ln + bi0 + row))*Ln + bj0;
        float* r1p = r0p + 8*Ln;
        #pragma unroll
        for (int ni = 0; ni < 8; ni++) {
            int col = wn*64 + ni*8 + cbase;
            float k0 = k2s[col], k1 = k2s[col + 1];
            float2 s0, s1;
            s0.x = 2.f*acc[mi][ni][0] - q2a - k0;
            s0.y = 2.f*acc[mi][ni][1] - q2a - k1;
            s1.x = 2.f*acc[mi][ni][2] - q2b - k0;
            s1.y = 2.f*acc[mi][ni][3] - q2b - k1;
            *(float2*)(r0p + col) = s0;
            *(float2*)(r1p + col) = s1;
            lsum += s0.x + s0.y + s1.x + s1.y;
            lsq  += s0.x*s0.x + s0.y*s0.y + s1.x*s1.x + s1.y*s1.y;
        }
    }
    double ds = (double)lsum, dq = (double)lsq;
    #pragma unroll
    for (int o = 16; o; o >>= 1) {
        ds += __shfl_xor_sync(0xffffffffu, ds, o);
        dq += __shfl_xor_sync(0xffffffffu, dq, o);
    }
    if (lane == 0) { rs[warp] = ds; rq[warp] = dq; }
    __syncthreads();
    if (tid == 0) {
        atomicAdd(&g_sum1[h], rs[0]+rs[1]+rs[2]+rs[3]);
        atomicAdd(&g_sumsq1[h], rq[0]+rq[1]+rq[2]+rq[3]);
    }
}

// ---------------- BN1 stats finalize ----------------
__global__ void stats1_kernel(const float* __restrict__ g1, const float* __restrict__ b1) {
    int h = threadIdx.x;
    if (h < Hn) {
        double n = (double)Bn*Ln*Ln;
        double m = g_sum1[h]/n;
        double var = g_sumsq1[h]/n - m*m;
        float rstd = (float)rsqrt(var + (double)EPSf);
        g_scale1[h] = g1[h]*rstd;
        g_shift1[h] = b1[h] - (float)m*rstd*g1[h];
    }
}

// ---------------- softmax: in-place, one row/warp, per-warp partials ----------------
__global__ void __launch_bounds__(512) softmax_kernel(float* __restrict__ co) {
    extern __shared__ char sm[];
    float (*red)[Ln] = (float(*)[Ln])sm;            // 16 x 1024 floats
    unsigned char* sval = (unsigned char*)(sm + 16*Ln*4);
    int bh = blockIdx.x >> 6;
    int rb = blockIdx.x & 63;
    int b = bh / Hn, h = bh % Hn;
    int tid = threadIdx.x, warp = tid >> 5, lane = tid & 31;
    for (int j = tid; j < Ln; j += 512) sval[j] = g_valid[b*Ln + j];
    __syncthreads();

    int i = rb*16 + warp;
    bool rowvalid = sval[i] != 0;
    float scale = g_scale1[h], shift = g_shift1[h];
    float4* Sr = (float4*)(co + ((size_t)bh*Ln + i)*Ln);

    float v[32];
    float sum = 0.f;
    #pragma unroll
    for (int c = 0; c < 8; c++) {
        float4 x = Sr[c*32 + lane];
        int j0 = c*128 + lane*4;
        float e0 = (rowvalid && sval[j0+0]) ? __expf(x.x*scale + shift) : 1.f;
        float e1 = (rowvalid && sval[j0+1]) ? __expf(x.y*scale + shift) : 1.f;
        float e2 = (rowvalid && sval[j0+2]) ? __expf(x.z*scale + shift) : 1.f;
        float e3 = (rowvalid && sval[j0+3]) ? __expf(x.w*scale + shift) : 1.f;
        v[c*4+0]=e0; v[c*4+1]=e1; v[c*4+2]=e2; v[c*4+3]=e3;
        sum += e0 + e1 + e2 + e3;
    }
    #pragma unroll
    for (int o = 16; o; o >>= 1) sum += __shfl_xor_sync(0xffffffffu, sum, o);
    float inv = 1.0f / sum;

    #pragma unroll
    for (int c = 0; c < 8; c++) {
        int j0 = c*128 + lane*4;
        float4 o4;
        o4.x = v[c*4+0]*inv; o4.y = v[c*4+1]*inv;
        o4.z = v[c*4+2]*inv; o4.w = v[c*4+3]*inv;
        Sr[c*32 + lane] = o4;
        *(float4*)&red[warp][j0] = o4;
    }
    __syncthreads();

    if (tid < 256) {
        int j = tid*4;
        float4 a = *(float4*)&red[0][j];
        #pragma unroll
        for (int w = 1; w < 16; w++) {
            float4 x = *(float4*)&red[w][j];
            a.x += x.x; a.y += x.y; a.z += x.z; a.w += x.w;
        }
        atomicAdd(&g_w[bh*Ln + j + 0], a.x);
        atomicAdd(&g_w[bh*Ln + j + 1], a.y);
        atomicAdd(&g_w[bh*Ln + j + 2], a.z);
        atomicAdd(&g_w[bh*Ln + j + 3], a.w);
    }
}

// ---------------- BN2 stats ----------------
__global__ void stats2_kernel(const float* __restrict__ g2, const float* __restrict__ b2) {
    int h = blockIdx.x;
    int tid = threadIdx.x;
    float ls = 0.f, lq = 0.f;
    for (int b = 0; b < Bn; b++) {
        const float* wp = g_w + (b*Hn + h)*Ln;
        for (int j = tid; j < Ln; j += 256) { float x = wp[j]; ls += x; lq += x*x; }
    }
    double ds = (double)ls, dq = (double)lq;
    #pragma unroll
    for (int o = 16; o; o >>= 1) {
        ds += __shfl_xor_sync(0xffffffffu, ds, o);
        dq += __shfl_xor_sync(0xffffffffu, dq, o);
    }
    __shared__ double rs[8], rq[8];
    int warp = tid >> 5, lane = tid & 31;
    if (lane == 0) { rs[warp] = ds; rq[warp] = dq; }
    __syncthreads();
    if (tid == 0) {
        double S = 0.0, Q2 = 0.0;
        for (int wgi = 0; wgi < 8; wgi++) { S += rs[wgi]; Q2 += rq[wgi]; }
        double n = (double)Bn*Ln;
        double m = S/n;
        double var = Q2/n - m*m;
        float rstd = (float)rsqrt(var + (double)EPSf);
        g_scale2[h] = g2[h]*rstd;
        g_shift2[h] = b2[h] - (float)m*rstd*g2[h];
    }
}

// ---------------- posterior gate ----------------
__global__ void gate_kernel(const float* __restrict__ Wp, const float* __restrict__ bp) {
    int idx = blockIdx.x*blockDim.x + threadIdx.x;
    if (idx >= Bn*Ln) return;
    int b = idx >> 10, l = idx & (Ln-1);
    float z0 = bp[0], z1 = bp[1];
    #pragma unroll
    for (int h = 0; h < Hn; h++) {
        float wn = g_w[(b*Hn + h)*Ln + l]*g_scale2[h] + g_shift2[h];
        z0 += Wp[h]      * wn;
        z1 += Wp[Hn + h] * wn;
    }
    float d = z1 - z0;
    g_p[idx] = 1.f/(1.f + __expf(d));
}

// ---------------- final masked softmax ----------------
__global__ void final_kernel(float* __restrict__ out) {
    int b = blockIdx.x, l = threadIdx.x;
    __shared__ float redm[32], redsum[32], bc[2];
    const float NEG_INF = __int_as_float(0xff800000);
    float x = g_valid[b*Ln + l] ? g_p[b*Ln + l] : NEG_INF;
    int warp = l >> 5, lane = l & 31;
    float m = x;
    #pragma unroll
    for (int o = 16; o; o >>= 1) m = fmaxf(m, __shfl_xor_sync(0xffffffffu, m, o));
    if (lane == 0) redm[warp] = m;
    __syncthreads();
    if (warp == 0) {
        m = redm[lane];
        #pragma unroll
        for (int o = 16; o; o >>= 1) m = fmaxf(m, __shfl_xor_sync(0xffffffffu, m, o));
        if (lane == 0) bc[0] = m;
    }
    __syncthreads();
    m = bc[0];
    float e = __expf(x - m);
    float s = e;
    #pragma unroll
    for (int o = 16; o; o >>= 1) s += __shfl_xor_sync(0xffffffffu, s, o);
    if (lane == 0) redsum[warp] = s;
    __syncthreads();
    if (warp == 0) {
        s = redsum[lane];
        #pragma unroll
        for (int o = 16; o; o >>= 1) s += __shfl_xor_sync(0xffffffffu, s, o);
        if (lane == 0) bc[1] = s;
    }
    __syncthreads();
    out[OFF_W + b*Ln + l] = e / bc[1];
}

// ---------------- launch ----------------
extern "C" void kernel_launch(void* const* d_in, const int* in_sizes, int n_in,
                              void* d_out, int out_size) {
    const float* Q  = (const float*)d_in[0];
    const float* K  = (const float*)d_in[1];
    const float* V  = (const float*)d_in[2];
    const unsigned int* bx = (const unsigned int*)d_in[4];
    const float* g1 = (const float*)d_in[5];
    const float* b1 = (const float*)d_in[6];
    const float* g2 = (const float*)d_in[7];
    const float* b2 = (const float*)d_in[8];
    const float* Wp = (const float*)d_in[9];
    const float* bp = (const float*)d_in[10];
    float* out = (float*)d_out;

    const int SMG = 2*128*GLDH*2;        // 69632
    const int SMS = 16*Ln*4 + Ln;        // 66560
    cudaFuncSetAttribute(gemm_kernel, cudaFuncAttributeMaxDynamicSharedMemorySize, SMG);
    cudaFuncSetAttribute(softmax_kernel, cudaFuncAttributeMaxDynamicSharedMemorySize, SMS);

    sq_kernel<<<1024 + 97, 256>>>(Q, K, bx);
    vout_kernel<<<(BHn*Ln*DHn/4 + 255)/256, 256>>>(V, out);
    gemm_kernel<<<dim3(Ln/128, Ln/128, BHn), 128, SMG>>>(Q, K, out);
    stats1_kernel<<<1, 32>>>(g1, b1);
    softmax_kernel<<<BHn*64, 512, SMS>>>(out);
    stats2_kernel<<<Hn, 256>>>(g2, b2);
    gate_kernel<<<(Bn*Ln + 255)/256, 256>>>(Wp, bp);
    final_kernel<<<Bn, Ln>>>(out);
}

// round 17
// speedup vs baseline: 1.3385x; 1.0204x over previous
#include <cuda_runtime.h>
#include <cuda_fp16.h>
#include <cstdint>

#define Bn  4
#define Ln  1024
#define Dn  768
#define Hn  6
#define DHn 128
#define BHn (Bn*Hn)
#define EPSf 1e-5f
#define GLDH 136   /* half leading dim: 128 + 8 */

#define OFF_CO 0
#define OFF_W  (BHn*Ln*Ln)          /* 25165824 */
#define OFF_V  (OFF_W + Bn*Ln)      /* 25169920 */

// ---------------- scratch ----------------
__device__ float  g_q2[BHn*Ln];
__device__ float  g_k2[BHn*Ln];
__device__ double g_sum1[Hn];
__device__ double g_sumsq1[Hn];
__device__ float  g_scale1[Hn];
__device__ float  g_shift1[Hn];
__device__ float  g_w[BHn*Ln];
__device__ unsigned char g_valid[Bn*Ln];

// ---------------- PTX: ldmatrix + mma ----------------
__device__ __forceinline__ void ldsm_x4(uint32_t& r0, uint32_t& r1, uint32_t& r2, uint32_t& r3,
                                        uint32_t addr) {
    asm volatile("ldmatrix.sync.aligned.m8n8.x4.shared.b16 {%0,%1,%2,%3}, [%4];"
                 : "=r"(r0), "=r"(r1), "=r"(r2), "=r"(r3) : "r"(addr));
}
__device__ __forceinline__ void mma16816(float* c, uint32_t a0, uint32_t a1, uint32_t a2,
                                         uint32_t a3, uint32_t b0, uint32_t b1) {
    asm volatile("mma.sync.aligned.m16n8k16.row.col.f32.f16.f16.f32 "
                 "{%0,%1,%2,%3}, {%4,%5,%6,%7}, {%8,%9}, {%0,%1,%2,%3};"
                 : "+f"(c[0]), "+f"(c[1]), "+f"(c[2]), "+f"(c[3])
                 : "r"(a0), "r"(a1), "r"(a2), "r"(a3), "r"(b0), "r"(b1));
}
__device__ __forceinline__ uint32_t smem_u32(const void* p) {
    return (uint32_t)__cvta_generic_to_shared(p);
}

// ---------------- sq + prep fused ----------------
__global__ void sq_kernel(const float* __restrict__ Q, const float* __restrict__ K,
                          const unsigned int* __restrict__ w) {
    if (blockIdx.x >= 1024) {
        int bidx = blockIdx.x - 1024;
        if (bidx < 96) {
            int idx = bidx*256 + threadIdx.x;
            g_w[idx] = 0.f;
            if (idx < Hn) { g_sum1[idx] = 0.0; g_sumsq1[idx] = 0.0; }
            return;
        }
        __shared__ int s_float, s_byte;
        if (threadIdx.x == 0) { s_float = 0; s_byte = 0; }
        __syncthreads();
        for (int i = threadIdx.x; i < (Bn*Ln)/4; i += blockDim.x) {
            unsigned v = w[i];
            if (v == 0x3f800000u) atomicOr(&s_float, 1);
            else if (v > 1u)      atomicOr(&s_byte, 1);
        }
        __syncthreads();
        int byte_mode = (!s_float) && s_byte;
        const unsigned char* bytes = (const unsigned char*)w;
        for (int i = threadIdx.x; i < Bn*Ln; i += blockDim.x) {
            bool padded = byte_mode ? (bytes[i] != 0) : (w[i] != 0u);
            g_valid[i] = padded ? 0 : 1;
        }
        return;
    }
    int gw = (blockIdx.x*blockDim.x + threadIdx.x) >> 5;
    int lane = threadIdx.x & 31;
    int t = gw / (Bn*Ln);
    int r = gw % (Bn*Ln);
    const float* src = (t ? K : Q) + (size_t)r*Dn;
    float* dst = t ? g_k2 : g_q2;
    int b = r >> 10, l = r & (Ln-1);
    float4 x[Hn];
    #pragma unroll
    for (int hh = 0; hh < Hn; hh++) x[hh] = ((const float4*)src)[hh*32 + lane];
    #pragma unroll
    for (int hh = 0; hh < Hn; hh++) {
        float s = x[hh].x*x[hh].x + x[hh].y*x[hh].y + x[hh].z*x[hh].z + x[hh].w*x[hh].w;
        #pragma unroll
        for (int o = 16; o; o >>= 1) s += __shfl_xor_sync(0xffffffffu, s, o);
        if (lane == 0) dst[(b*Hn + hh)*Ln + l] = s;
    }
}

// ---------------- Vh output: transpose copy ----------------
__global__ void vout_kernel(const float* __restrict__ V, float* __restrict__ out) {
    int idx = blockIdx.x*blockDim.x + threadIdx.x;
    if (idx >= BHn*Ln*DHn/4) return;
    int d4 = idx & 31;
    int l  = (idx >> 5) & (Ln-1);
    int h  = (idx >> 15) % Hn;
    int b  = idx / (32*Ln*Hn);
    float4 v = *(const float4*)(V + ((size_t)(b*Ln + l))*Dn + h*DHn + d4*4);
    ((float4*)(out + OFF_V))[idx] = v;
}

// ---------------- main GEMM (raw mma): CTA 128x128, 128 thr, warp 64x64 ----------------
__global__ void __launch_bounds__(128, 2) gemm_kernel(const float* __restrict__ Q,
                                                      const float* __restrict__ K,
                                                      float* __restrict__ co) {
    extern __shared__ char smraw[];
    __half* As = (__half*)smraw;                    // 128 x GLDH
    __half* Bs = As + 128*GLDH;
    __shared__ float q2s[128], k2s[128];
    __shared__ double rs[4], rq[4];

    int bh = blockIdx.z; int b = bh / Hn, h = bh % Hn;
    int bi0 = blockIdx.y*128, bj0 = blockIdx.x*128;
    const float* Qb = Q + (size_t)b*Ln*Dn + h*DHn;
    const float* Kb = K + (size_t)b*Ln*Dn + h*DHn;
    int tid = threadIdx.x, warp = tid >> 5, lane = tid & 31;

    q2s[tid] = g_q2[bh*Ln + bi0 + tid];
    k2s[tid] = g_k2[bh*Ln + bj0 + tid];

    #pragma unroll
    for (int i = 0; i < 32; i++) {
        int t = tid + i*128;
        int r = t >> 5, c = t & 31;
        float4 q = *(const float4*)(Qb + (size_t)(bi0 + r)*Dn + c*4);
        *(half2*)&As[r*GLDH + c*4 + 0] = __floats2half2_rn(q.x, q.y);
        *(half2*)&As[r*GLDH + c*4 + 2] = __floats2half2_rn(q.z, q.w);
    }
    #pragma unroll
    for (int i = 0; i < 32; i++) {
        int t = tid + i*128;
        int r = t >> 5, c = t & 31;
        float4 k = *(const float4*)(Kb + (size_t)(bj0 + r)*Dn + c*4);
        *(half2*)&Bs[r*GLDH + c*4 + 0] = __floats2half2_rn(k.x, k.y);
        *(half2*)&Bs[r*GLDH + c*4 + 2] = __floats2half2_rn(k.z, k.w);
    }
    __syncthreads();

    int wm = warp & 1, wn = warp >> 1;
    uint32_t aBase = smem_u32(As) +
        (uint32_t)(((wm*64 + (lane & 15))*GLDH + (lane >> 4)*8) * 2);
    uint32_t bBase = smem_u32(Bs) +
        (uint32_t)(((wn*64 + (lane & 7) + ((lane >> 4) << 3))*GLDH + ((lane >> 3) & 1)*8) * 2);

    float acc[4][8][4];
    #pragma unroll
    for (int mi = 0; mi < 4; mi++)
        #pragma unroll
        for (int ni = 0; ni < 8; ni++)
            #pragma unroll
            for (int e = 0; e < 4; e++) acc[mi][ni][e] = 0.f;

    #pragma unroll
    for (int k = 0; k < 128; k += 16) {
        uint32_t a[4][4], bb[4][4];
        #pragma unroll
        for (int mi = 0; mi < 4; mi++)
            ldsm_x4(a[mi][0], a[mi][1], a[mi][2], a[mi][3],
                    aBase + (uint32_t)((mi*16*GLDH + k)*2));
        #pragma unroll
        for (int nj = 0; nj < 4; nj++)
            ldsm_x4(bb[nj][0], bb[nj][1], bb[nj][2], bb[nj][3],
                    bBase + (uint32_t)((nj*16*GLDH + k)*2));
        #pragma unroll
        for (int mi = 0; mi < 4; mi++)
            #pragma unroll
            for (int ni = 0; ni < 8; ni++) {
                int nj = ni >> 1;
                if (ni & 1)
                    mma16816(acc[mi][ni], a[mi][0], a[mi][1], a[mi][2], a[mi][3],
                             bb[nj][2], bb[nj][3]);
                else
                    mma16816(acc[mi][ni], a[mi][0], a[mi][1], a[mi][2], a[mi][3],
                             bb[nj][0], bb[nj][1]);
            }
    }

    int rbase = lane >> 2;
    int cbase = (lane & 3)*2;
    float lsum = 0.f, lsq = 0.f;
    #pragma unroll
    for (int mi = 0; mi < 4; mi++) {
        int row = wm*64 + mi*16 + rbase;
        float q2a = q2s[row], q2b = q2s[row + 8];
        float* r0p = co + ((size_t)(bh*Ln + bi0 + row))*Ln + bj0;
        float* r1p = r0p + 8*Ln;
        #pragma unroll
        for (int ni = 0; ni < 8; ni++) {
            int col = wn*64 + ni*8 + cbase;
            float k0 = k2s[col], k1 = k2s[col + 1];
            float2 s0, s1;
            s0.x = 2.f*acc[mi][ni][0] - q2a - k0;
            s0.y = 2.f*acc[mi][ni][1] - q2a - k1;
            s1.x = 2.f*acc[mi][ni][2] - q2b - k0;
            s1.y = 2.f*acc[mi][ni][3] - q2b - k1;
            *(float2*)(r0p + col) = s0;
            *(float2*)(r1p + col) = s1;
            lsum += s0.x + s0.y + s1.x + s1.y;
            lsq  += s0.x*s0.x + s0.y*s0.y + s1.x*s1.x + s1.y*s1.y;
        }
    }
    double ds = (double)lsum, dq = (double)lsq;
    #pragma unroll
    for (int o = 16; o; o >>= 1) {
        ds += __shfl_xor_sync(0xffffffffu, ds, o);
        dq += __shfl_xor_sync(0xffffffffu, dq, o);
    }
    if (lane == 0) { rs[warp] = ds; rq[warp] = dq; }
    __syncthreads();
    if (tid == 0) {
        atomicAdd(&g_sum1[h], rs[0]+rs[1]+rs[2]+rs[3]);
        atomicAdd(&g_sumsq1[h], rq[0]+rq[1]+rq[2]+rq[3]);
    }
}

// ---------------- BN1 stats finalize ----------------
__global__ void stats1_kernel(const float* __restrict__ g1, const float* __restrict__ b1) {
    int h = threadIdx.x;
    if (h < Hn) {
        double n = (double)Bn*Ln*Ln;
        double m = g_sum1[h]/n;
        double var = g_sumsq1[h]/n - m*m;
        float rstd = (float)rsqrt(var + (double)EPSf);
        g_scale1[h] = g1[h]*rstd;
        g_shift1[h] = b1[h] - (float)m*rstd*g1[h];
    }
}

// ---------------- softmax: in-place, one row/warp, per-warp partials ----------------
__global__ void __launch_bounds__(512) softmax_kernel(float* __restrict__ co) {
    extern __shared__ char sm[];
    float (*red)[Ln] = (float(*)[Ln])sm;            // 16 x 1024 floats
    unsigned char* sval = (unsigned char*)(sm + 16*Ln*4);
    int bh = blockIdx.x >> 6;
    int rb = blockIdx.x & 63;
    int b = bh / Hn, h = bh % Hn;
    int tid = threadIdx.x, warp = tid >> 5, lane = tid & 31;
    for (int j = tid; j < Ln; j += 512) sval[j] = g_valid[b*Ln + j];
    __syncthreads();

    int i = rb*16 + warp;
    bool rowvalid = sval[i] != 0;
    float scale = g_scale1[h], shift = g_shift1[h];
    float4* Sr = (float4*)(co + ((size_t)bh*Ln + i)*Ln);

    float v[32];
    float sum = 0.f;
    #pragma unroll
    for (int c = 0; c < 8; c++) {
        float4 x = Sr[c*32 + lane];
        int j0 = c*128 + lane*4;
        float e0 = (rowvalid && sval[j0+0]) ? __expf(x.x*scale + shift) : 1.f;
        float e1 = (rowvalid && sval[j0+1]) ? __expf(x.y*scale + shift) : 1.f;
        float e2 = (rowvalid && sval[j0+2]) ? __expf(x.z*scale + shift) : 1.f;
        float e3 = (rowvalid && sval[j0+3]) ? __expf(x.w*scale + shift) : 1.f;
        v[c*4+0]=e0; v[c*4+1]=e1; v[c*4+2]=e2; v[c*4+3]=e3;
        sum += e0 + e1 + e2 + e3;
    }
    #pragma unroll
    for (int o = 16; o; o >>= 1) sum += __shfl_xor_sync(0xffffffffu, sum, o);
    float inv = 1.0f / sum;

    #pragma unroll
    for (int c = 0; c < 8; c++) {
        int j0 = c*128 + lane*4;
        float4 o4;
        o4.x = v[c*4+0]*inv; o4.y = v[c*4+1]*inv;
        o4.z = v[c*4+2]*inv; o4.w = v[c*4+3]*inv;
        Sr[c*32 + lane] = o4;
        *(float4*)&red[warp][j0] = o4;
    }
    __syncthreads();

    if (tid < 256) {
        int j = tid*4;
        float4 a = *(float4*)&red[0][j];
        #pragma unroll
        for (int w = 1; w < 16; w++) {
            float4 x = *(float4*)&red[w][j];
            a.x += x.x; a.y += x.y; a.z += x.z; a.w += x.w;
        }
        atomicAdd(&g_w[bh*Ln + j + 0], a.x);
        atomicAdd(&g_w[bh*Ln + j + 1], a.y);
        atomicAdd(&g_w[bh*Ln + j + 2], a.z);
        atomicAdd(&g_w[bh*Ln + j + 3], a.w);
    }
}

// ---------------- tail: parallel stats2 + gate + final softmax; grid=Bn, 1024 thr ----------------
__global__ void __launch_bounds__(1024) tail_kernel(const float* __restrict__ g2,
                                                    const float* __restrict__ b2,
                                                    const float* __restrict__ Wp,
                                                    const float* __restrict__ bp,
                                                    float* __restrict__ out) {
    __shared__ double hsum[Hn], hsq[Hn];
    __shared__ float s_scale2[Hn], s_shift2[Hn];
    __shared__ float redd[32], bcast[2];
    int bb = blockIdx.x;
    int tid = threadIdx.x, warp = tid >> 5, lane = tid & 31;

    if (tid < Hn) { hsum[tid] = 0.0; hsq[tid] = 0.0; }
    __syncthreads();

    // stats2: 24 (head,batch) units, one warp each (warps 0-23)
    if (warp < Hn*Bn) {
        int h = warp / Bn, b = warp % Bn;
        const float* wp = g_w + (b*Hn + h)*Ln;
        float ls = 0.f, lq = 0.f;
        #pragma unroll
        for (int i = 0; i < 32; i++) {
            float x = wp[lane + i*32];
            ls += x; lq += x*x;
        }
        double ds = (double)ls, dq = (double)lq;
        #pragma unroll
        for (int o = 16; o; o >>= 1) {
            ds += __shfl_xor_sync(0xffffffffu, ds, o);
            dq += __shfl_xor_sync(0xffffffffu, dq, o);
        }
        if (lane == 0) { atomicAdd(&hsum[h], ds); atomicAdd(&hsq[h], dq); }
    }
    __syncthreads();
    if (tid < Hn) {
        double n = (double)Bn*Ln;
        double m = hsum[tid]/n;
        double var = hsq[tid]/n - m*m;
        float rstd = (float)rsqrt(var + (double)EPSf);
        s_scale2[tid] = g2[tid]*rstd;
        s_shift2[tid] = b2[tid] - (float)m*rstd*g2[tid];
    }
    __syncthreads();

    // gate for this batch
    int l = tid;
    float z0 = bp[0], z1 = bp[1];
    #pragma unroll
    for (int h = 0; h < Hn; h++) {
        float wn = g_w[(bb*Hn + h)*Ln + l]*s_scale2[h] + s_shift2[h];
        z0 += Wp[h]      * wn;
        z1 += Wp[Hn + h] * wn;
    }
    const float NEG_INF = __int_as_float(0xff800000);
    float p = 1.f/(1.f + __expf(z1 - z0));
    float x = g_valid[bb*Ln + l] ? p : NEG_INF;

    // final masked softmax over L
    float m = x;
    #pragma unroll
    for (int o = 16; o; o >>= 1) m = fmaxf(m, __shfl_xor_sync(0xffffffffu, m, o));
    if (lane == 0) redd[warp] = m;
    __syncthreads();
    if (warp == 0) {
        float mm = redd[lane];
        #pragma unroll
        for (int o = 16; o; o >>= 1) mm = fmaxf(mm, __shfl_xor_sync(0xffffffffu, mm, o));
        if (lane == 0) bcast[0] = mm;
    }
    __syncthreads();
    float e = __expf(x - bcast[0]);
    float s = e;
    #pragma unroll
    for (int o = 16; o; o >>= 1) s += __shfl_xor_sync(0xffffffffu, s, o);
    __syncthreads();
    if (lane == 0) redd[warp] = s;
    __syncthreads();
    if (warp == 0) {
        float ss = redd[lane];
        #pragma unroll
        for (int o = 16; o; o >>= 1) ss += __shfl_xor_sync(0xffffffffu, ss, o);
        if (lane == 0) bcast[1] = ss;
    }
    __syncthreads();
    out[OFF_W + bb*Ln + l] = e / bcast[1];
}

// ---------------- launch ----------------
extern "C" void kernel_launch(void* const* d_in, const int* in_sizes, int n_in,
                              void* d_out, int out_size) {
    const float* Q  = (const float*)d_in[0];
    const float* K  = (const float*)d_in[1];
    const float* V  = (const float*)d_in[2];
    const unsigned int* bx = (const unsigned int*)d_in[4];
    const float* g1 = (const float*)d_in[5];
    const float* b1 = (const float*)d_in[6];
    const float* g2 = (const float*)d_in[7];
    const float* b2 = (const float*)d_in[8];
    const float* Wp = (const float*)d_in[9];
    const float* bp = (const float*)d_in[10];
    float* out = (float*)d_out;

    const int SMG = 2*128*GLDH*2;        // 69632
    const int SMS = 16*Ln*4 + Ln;        // 66560
    cudaFuncSetAttribute(gemm_kernel, cudaFuncAttributeMaxDynamicSharedMemorySize, SMG);
    cudaFuncSetAttribute(softmax_kernel, cudaFuncAttributeMaxDynamicSharedMemorySize, SMS);

    sq_kernel<<<1024 + 97, 256>>>(Q, K, bx);
    vout_kernel<<<(BHn*Ln*DHn/4 + 255)/256, 256>>>(V, out);
    gemm_kernel<<<dim3(Ln/128, Ln/128, BHn), 128, SMG>>>(Q, K, out);
    stats1_kernel<<<1, 32>>>(g1, b1);
    softmax_kernel<<<BHn*64, 512, SMS>>>(out);
    tail_kernel<<<Bn, 1024>>>(g2, b2, Wp, bp, out);
}